// round 8
// baseline (speedup 1.0000x reference)
#include <cuda_runtime.h>
#include <cstdint>

// ---------------- problem constants ----------------
#define C_IN   256
#define C_OUT  256
#define PIXN   16384          // 64*256 pixels per (tensor, batch)
#define HOUTN  768
#define WwN    256

// ---------------- tiling ----------------
// CTA: 256 out-ch x 128 pixels, K chunks of 32. 16 warps (512 thr), warp tile 64x32.
#define KB      32
#define NKS     4             // k-steps of 8 per chunk
#define NCHUNK  8
#define RPX     136           // X row stride floats: 136 % 32 == 8 -> conflict-free B frags
#define W_STAGE 32768         // fragment-packed W chunk: 256 m x 32 k x 4B
#define X_STAGE (KB*RPX*4)    // 17408 B
#define STAGE_B (W_STAGE + X_STAGE)
#define NSTAGE  3
#define SMEM_BYTES (NSTAGE * STAGE_B)   // 150528

// W fragment-packed: float4 slot within chunk = (mb16*4 + ksi)*32 + lane
__device__ float g_Wp[C_IN * C_OUT];

struct XPtrs { const float* p[12]; };

__device__ __forceinline__ uint32_t f2tf32(float v) {
    uint32_t r; asm("cvt.rna.tf32.f32 %0, %1;" : "=r"(r) : "f"(v)); return r;
}
__device__ __forceinline__ void mma_tf32(float& d0, float& d1, float& d2, float& d3,
                                         uint32_t a0, uint32_t a1, uint32_t a2, uint32_t a3,
                                         uint32_t b0, uint32_t b1) {
    asm volatile(
        "mma.sync.aligned.m16n8k8.row.col.f32.tf32.tf32.f32 "
        "{%0,%1,%2,%3},{%4,%5,%6,%7},{%8,%9},{%0,%1,%2,%3};"
        : "+f"(d0), "+f"(d1), "+f"(d2), "+f"(d3)
        : "r"(a0), "r"(a1), "r"(a2), "r"(a3), "r"(b0), "r"(b1));
}
__device__ __forceinline__ void cp16(void* s, const float* g) {
    uint32_t sa = (uint32_t)__cvta_generic_to_shared(s);
    asm volatile("cp.async.cg.shared.global [%0], [%1], 16;\n" :: "r"(sa), "l"(g));
}

// ---- pre-kernel: pack W[c][o] into per-thread tf32 fragment quads ----
// packed float index t: j=t&3, lane=(t>>2)&31, ksi=(t>>7)&3, mb16=(t>>9)&15, kc=t>>13
// quad of (kc,mb16,ksi,lane): {W[k][m], W[k][m+8], W[k+4][m], W[k+4][m+8]}
__global__ void wpack_kernel(const float* __restrict__ W) {
    int t    = blockIdx.x * 256 + threadIdx.x;
    int j    = t & 3;
    int lane = (t >> 2) & 31;
    int ksi  = (t >> 7) & 3;
    int mb16 = (t >> 9) & 15;
    int kc   = t >> 13;
    int gid = lane >> 2, tig = lane & 3;
    int m = mb16 * 16 + gid + (j & 1) * 8;
    int k = kc * KB + ksi * 8 + tig + (j >> 1) * 4;
    g_Wp[t] = __uint_as_float(f2tf32(W[k * C_OUT + m]));
}

// ---- main kernel ----
__global__ void __launch_bounds__(512, 1)
conv_interleave_kernel(XPtrs xs, const float* __restrict__ bg, float* __restrict__ out)
{
    extern __shared__ char smem[];

    const int tid  = threadIdx.x;
    const int lane = tid & 31;
    const int warp = tid >> 5;        // 0..15
    const int gid  = lane >> 2;
    const int tig  = lane & 3;

    const int p0 = blockIdx.x * 128;
    const int z  = blockIdx.y;        // 0..23
    const int ii = z >> 1;
    const int bb = z & 1;
    const float* Xg = xs.p[ii] + (size_t)bb * (C_IN * PIXN);

    const int warp_m = (warp >> 2) * 64;    // out-channel base (0..192)
    const int wm16   = (warp >> 2) * 4;     // m16-block base
    const int warp_n = (warp & 3) * 32;     // pixel base (0..96)

    float d[4][4][4];
    #pragma unroll
    for (int mb = 0; mb < 4; ++mb)
        #pragma unroll
        for (int nb = 0; nb < 4; ++nb)
            #pragma unroll
            for (int r = 0; r < 4; ++r) d[mb][nb][r] = 0.0f;

    // ---- stage loader (512 threads) ----
    auto load_stage = [&](int ch) {
        const int st = ch % NSTAGE;
        char* wdst = smem + st * STAGE_B;
        char* xdst = wdst + W_STAGE;
        const float* wsrc = g_Wp + ch * (KB * C_OUT);
        #pragma unroll
        for (int it = 0; it < 4; ++it) {           // W: 2048 x 16B, linear
            int idx = it * 512 + tid;
            cp16(wdst + idx * 16, wsrc + idx * 4);
        }
        #pragma unroll
        for (int it = 0; it < 2; ++it) {           // X: 32 rows x 512B (row pad 544B)
            int idx = it * 512 + tid;
            int k = idx >> 5, q = idx & 31;
            cp16(xdst + k * (RPX * 4) + q * 16,
                 Xg + (size_t)(ch * KB + k) * PIXN + p0 + q * 4);
        }
        asm volatile("cp.async.commit_group;");
    };

    load_stage(0);
    load_stage(1);

    #pragma unroll 1
    for (int ch = 0; ch < NCHUNK; ++ch) {
        asm volatile("cp.async.wait_group 1;");
        __syncthreads();

        const int s = ch % NSTAGE;
        if (ch + 2 < NCHUNK) load_stage(ch + 2);

        const float4* Wf4 = (const float4*)(smem + s * STAGE_B);
        const float*  Xst = (const float*)(smem + s * STAGE_B + W_STAGE);

        #pragma unroll
        for (int ksi = 0; ksi < NKS; ++ksi) {
            const int kr = ksi * 8 + tig;

            // A fragments: packed tf32 quads, one LDS.128 per m16-block
            float4 aq[4];
            #pragma unroll
            for (int mb = 0; mb < 4; ++mb)
                aq[mb] = Wf4[((wm16 + mb) * 4 + ksi) * 32 + lane];

            // B fragments: conflict-free LDS.32 + cvt
            uint32_t bt[8];
            #pragma unroll
            for (int nb = 0; nb < 4; ++nb) {
                const int n = warp_n + nb * 8 + gid;
                bt[2 * nb]     = f2tf32(Xst[kr * RPX + n]);
                bt[2 * nb + 1] = f2tf32(Xst[(kr + 4) * RPX + n]);
            }

            #pragma unroll
            for (int mb = 0; mb < 4; ++mb) {
                const uint32_t a0 = __float_as_uint(aq[mb].x);
                const uint32_t a1 = __float_as_uint(aq[mb].y);
                const uint32_t a2 = __float_as_uint(aq[mb].z);
                const uint32_t a3 = __float_as_uint(aq[mb].w);
                #pragma unroll
                for (int nb = 0; nb < 4; ++nb)
                    mma_tf32(d[mb][nb][0], d[mb][nb][1], d[mb][nb][2], d[mb][nb][3],
                             a0, a1, a2, a3, bt[2 * nb], bt[2 * nb + 1]);
            }
        }
        __syncthreads();   // all warps done with stage s before refill
    }

    // ---- epilogue: interleaved scatter + bias*count ----
    #pragma unroll
    for (int mb = 0; mb < 4; ++mb) {
        const int o = warp_m + mb * 16 + gid;
        const float bv0 = __ldg(bg + o);
        const float bv1 = __ldg(bg + o + 8);
        #pragma unroll
        for (int nb = 0; nb < 4; ++nb) {
            const int p = p0 + warp_n + nb * 8 + 2 * tig;
            const int h = p >> 8;
            const int w = p & 255;
            const int r = 12 * h + ii;
            const int cnt = min(11, r) - max(0, r - (HOUTN - 12)) + 1;
            const float fc = (float)cnt;
            const float bias0 = bv0 * fc;
            const float bias1 = bv1 * fc;
            const size_t base = ((size_t)(bb * C_OUT + o) * HOUTN + r) * WwN + w;
            float2 v0 = make_float2(d[mb][nb][0] + bias0, d[mb][nb][1] + bias0);
            float2 v1 = make_float2(d[mb][nb][2] + bias1, d[mb][nb][3] + bias1);
            *reinterpret_cast<float2*>(out + base) = v0;
            *reinterpret_cast<float2*>(out + base + (size_t)8 * HOUTN * WwN) = v1;
        }
    }
}

extern "C" void kernel_launch(void* const* d_in, const int* in_sizes, int n_in,
                              void* d_out, int out_size)
{
    (void)in_sizes; (void)n_in; (void)out_size;

    XPtrs xs;
    for (int i = 0; i < 12; ++i) xs.p[i] = (const float*)d_in[i];
    const float* W = (const float*)d_in[12];
    const float* b = (const float*)d_in[13];
    float* out = (float*)d_out;

    wpack_kernel<<<256, 256>>>(W);

    cudaFuncSetAttribute(conv_interleave_kernel,
                         cudaFuncAttributeMaxDynamicSharedMemorySize, SMEM_BYTES);
    dim3 grid(PIXN / 128, 24, 1);   // 128 x 24 = 3072 CTAs
    conv_interleave_kernel<<<grid, 512, SMEM_BYTES>>>(xs, b, out);
}

// round 9
// speedup vs baseline: 1.1575x; 1.1575x over previous
#include <cuda_runtime.h>
#include <cstdint>

// ---------------- problem constants ----------------
#define C_IN   256
#define C_OUT  256
#define PIXN   16384          // 64*256 pixels per (tensor, batch)
#define HOUTN  768
#define WwN    256

// ---------------- tiling ----------------
// CTA: 128 out-ch x 128 pixels, K chunks of 32. 8 warps, warp tile 64x32.
// 3-stage pipeline, 99KB smem -> 2 CTAs per SM.
#define KB      32
#define NKS     4             // k-steps of 8 per chunk
#define NCHUNK  8
#define RPX     136           // X row stride floats: 136 % 32 == 8 -> conflict-free B frags
#define W_STAGE 16384         // fragment-packed W chunk: 128 m x 32 k x 4B
#define X_STAGE (KB*RPX*4)    // 17408 B
#define STAGE_B (W_STAGE + X_STAGE)     // 33792
#define NSTAGE  3
#define SMEM_BYTES (NSTAGE * STAGE_B)   // 101376 -> 2 CTAs/SM

// W fragment-packed over full 256 m: float4 slot within chunk = (mb16*4 + ksi)*32 + lane
__device__ float g_Wp[C_IN * C_OUT];

struct XPtrs { const float* p[12]; };

__device__ __forceinline__ uint32_t f2tf32(float v) {
    uint32_t r; asm("cvt.rna.tf32.f32 %0, %1;" : "=r"(r) : "f"(v)); return r;
}
__device__ __forceinline__ void mma_tf32(float& d0, float& d1, float& d2, float& d3,
                                         uint32_t a0, uint32_t a1, uint32_t a2, uint32_t a3,
                                         uint32_t b0, uint32_t b1) {
    asm volatile(
        "mma.sync.aligned.m16n8k8.row.col.f32.tf32.tf32.f32 "
        "{%0,%1,%2,%3},{%4,%5,%6,%7},{%8,%9},{%0,%1,%2,%3};"
        : "+f"(d0), "+f"(d1), "+f"(d2), "+f"(d3)
        : "r"(a0), "r"(a1), "r"(a2), "r"(a3), "r"(b0), "r"(b1));
}
__device__ __forceinline__ void cp16(void* s, const float* g) {
    uint32_t sa = (uint32_t)__cvta_generic_to_shared(s);
    asm volatile("cp.async.cg.shared.global [%0], [%1], 16;\n" :: "r"(sa), "l"(g));
}

// ---- pre-kernel: pack W[c][o] into per-thread tf32 fragment quads ----
// packed float index t: j=t&3, lane=(t>>2)&31, ksi=(t>>7)&3, mb16=(t>>9)&15, kc=t>>13
// quad of (kc,mb16,ksi,lane): {W[k][m], W[k][m+8], W[k+4][m], W[k+4][m+8]}
__global__ void wpack_kernel(const float* __restrict__ W) {
    int t    = blockIdx.x * 256 + threadIdx.x;
    int j    = t & 3;
    int lane = (t >> 2) & 31;
    int ksi  = (t >> 7) & 3;
    int mb16 = (t >> 9) & 15;
    int kc   = t >> 13;
    int gid = lane >> 2, tig = lane & 3;
    int m = mb16 * 16 + gid + (j & 1) * 8;
    int k = kc * KB + ksi * 8 + tig + (j >> 1) * 4;
    g_Wp[t] = __uint_as_float(f2tf32(W[k * C_OUT + m]));
}

// ---- main kernel ----
__global__ void __launch_bounds__(256, 2)
conv_interleave_kernel(XPtrs xs, const float* __restrict__ bg, float* __restrict__ out)
{
    extern __shared__ char smem[];

    const int tid  = threadIdx.x;
    const int lane = tid & 31;
    const int warp = tid >> 5;        // 0..7
    const int gid  = lane >> 2;
    const int tig  = lane & 3;

    // pair the two out-channel halves of a pixel tile adjacently -> co-resident, X hits L2
    const int bx  = blockIdx.x;       // 0..255
    const int p0  = (bx >> 1) * 128;  // pixel tile base
    const int cht = bx & 1;           // out-channel half (0 or 1)
    const int z   = blockIdx.y;       // 0..23
    const int ii  = z >> 1;
    const int bb  = z & 1;
    const float* Xg = xs.p[ii] + (size_t)bb * (C_IN * PIXN);

    const int warp_m = (warp >> 2) * 64;    // local out-channel base (0 or 64)
    const int wm16   = (warp >> 2) * 4;     // local m16-block base
    const int warp_n = (warp & 3) * 32;     // pixel base (0..96)

    float d[4][4][4];
    #pragma unroll
    for (int mb = 0; mb < 4; ++mb)
        #pragma unroll
        for (int nb = 0; nb < 4; ++nb)
            #pragma unroll
            for (int r = 0; r < 4; ++r) d[mb][nb][r] = 0.0f;

    // ---- stage loader (256 threads): W half-chunk 1024 float4, X chunk 1024 float4 ----
    auto load_stage = [&](int ch) {
        const int st = ch % NSTAGE;
        char* wdst = smem + st * STAGE_B;
        char* xdst = wdst + W_STAGE;
        // this cht's mb16 range is slots [cht*1024, cht*1024+1024) within the chunk's 2048
        const float* wsrc = g_Wp + ch * (KB * C_OUT) + cht * 4096;
        #pragma unroll
        for (int it = 0; it < 4; ++it) {           // W: 1024 x 16B, linear
            int idx = it * 256 + tid;
            cp16(wdst + idx * 16, wsrc + idx * 4);
        }
        #pragma unroll
        for (int it = 0; it < 4; ++it) {           // X: 32 rows x 512B (row pad 544B)
            int idx = it * 256 + tid;
            int k = idx >> 5, q = idx & 31;
            cp16(xdst + k * (RPX * 4) + q * 16,
                 Xg + (size_t)(ch * KB + k) * PIXN + p0 + q * 4);
        }
        asm volatile("cp.async.commit_group;");
    };

    load_stage(0);
    load_stage(1);

    #pragma unroll 1
    for (int ch = 0; ch < NCHUNK; ++ch) {
        asm volatile("cp.async.wait_group 1;");
        __syncthreads();
        // single barrier per chunk: all warps have finished chunk ch-1, whose
        // stage (ch-1)%3 == (ch+2)%3 is exactly the one we now refill.
        const int s = ch % NSTAGE;
        if (ch + 2 < NCHUNK) load_stage(ch + 2);

        const float4* Wf4 = (const float4*)(smem + s * STAGE_B);
        const float*  Xst = (const float*)(smem + s * STAGE_B + W_STAGE);

        #pragma unroll
        for (int ksi = 0; ksi < NKS; ++ksi) {
            const int kr = ksi * 8 + tig;

            // A fragments: packed tf32 quads, one LDS.128 per m16-block
            float4 aq[4];
            #pragma unroll
            for (int mb = 0; mb < 4; ++mb)
                aq[mb] = Wf4[((wm16 + mb) * 4 + ksi) * 32 + lane];

            // B fragments: conflict-free LDS.32 + cvt
            uint32_t bt[8];
            #pragma unroll
            for (int nb = 0; nb < 4; ++nb) {
                const int n = warp_n + nb * 8 + gid;
                bt[2 * nb]     = f2tf32(Xst[kr * RPX + n]);
                bt[2 * nb + 1] = f2tf32(Xst[(kr + 4) * RPX + n]);
            }

            #pragma unroll
            for (int mb = 0; mb < 4; ++mb) {
                const uint32_t a0 = __float_as_uint(aq[mb].x);
                const uint32_t a1 = __float_as_uint(aq[mb].y);
                const uint32_t a2 = __float_as_uint(aq[mb].z);
                const uint32_t a3 = __float_as_uint(aq[mb].w);
                #pragma unroll
                for (int nb = 0; nb < 4; ++nb)
                    mma_tf32(d[mb][nb][0], d[mb][nb][1], d[mb][nb][2], d[mb][nb][3],
                             a0, a1, a2, a3, bt[2 * nb], bt[2 * nb + 1]);
            }
        }
    }

    // ---- epilogue: interleaved scatter + bias*count ----
    #pragma unroll
    for (int mb = 0; mb < 4; ++mb) {
        const int o = cht * 128 + warp_m + mb * 16 + gid;
        const float bv0 = __ldg(bg + o);
        const float bv1 = __ldg(bg + o + 8);
        #pragma unroll
        for (int nb = 0; nb < 4; ++nb) {
            const int p = p0 + warp_n + nb * 8 + 2 * tig;
            const int h = p >> 8;
            const int w = p & 255;
            const int r = 12 * h + ii;
            const int cnt = min(11, r) - max(0, r - (HOUTN - 12)) + 1;
            const float fc = (float)cnt;
            const float bias0 = bv0 * fc;
            const float bias1 = bv1 * fc;
            const size_t base = ((size_t)(bb * C_OUT + o) * HOUTN + r) * WwN + w;
            float2 v0 = make_float2(d[mb][nb][0] + bias0, d[mb][nb][1] + bias0);
            float2 v1 = make_float2(d[mb][nb][2] + bias1, d[mb][nb][3] + bias1);
            *reinterpret_cast<float2*>(out + base) = v0;
            *reinterpret_cast<float2*>(out + base + (size_t)8 * HOUTN * WwN) = v1;
        }
    }
}

extern "C" void kernel_launch(void* const* d_in, const int* in_sizes, int n_in,
                              void* d_out, int out_size)
{
    (void)in_sizes; (void)n_in; (void)out_size;

    XPtrs xs;
    for (int i = 0; i < 12; ++i) xs.p[i] = (const float*)d_in[i];
    const float* W = (const float*)d_in[12];
    const float* b = (const float*)d_in[13];
    float* out = (float*)d_out;

    wpack_kernel<<<256, 256>>>(W);

    cudaFuncSetAttribute(conv_interleave_kernel,
                         cudaFuncAttributeMaxDynamicSharedMemorySize, SMEM_BYTES);
    dim3 grid(256, 24, 1);   // (pixel-tile, ch-half) pairs x 24
    conv_interleave_kernel<<<grid, 256, SMEM_BYTES>>>(xs, b, out);
}

// round 10
// speedup vs baseline: 1.4503x; 1.2530x over previous
#include <cuda_runtime.h>
#include <cuda_fp16.h>
#include <cstdint>

// ---------------- problem constants ----------------
#define C_IN   256
#define C_OUT  256
#define PIXN   16384          // 64*256 pixels per (tensor, batch)
#define HOUTN  768
#define WwN    256

// ---------------- tiling ----------------
// CTA: 128 out-ch x 128 pixels, K chunks of 32 (2 x k16 steps). 8 warps, warp tile 64x32.
// fp16 m16n8k16 HMMA, fp32 accumulate. 3-stage W (cp.async) + 1-ahead X (LDG/cvt/STS).
#define KB      32
#define NCHUNK  8
#define RPXH    136           // X row stride in uint32(fp16x2): 136 % 32 == 8 -> conflict-free
#define W_STAGE 8192          // fp16 fragment-packed W chunk: 512 uint4
#define X_STAGE (16*RPXH*4)   // 16 k2-rows x 136 uint32 = 8704 B
#define STAGE_B (W_STAGE + X_STAGE)     // 16896
#define NSTAGE  3
#define SMEM_BYTES (NSTAGE * STAGE_B)   // 50688 -> 2 CTAs/SM (reg-capped)

// W fragment quads, fp16x2: uint4 index = ((ch*2+cht)*8 + mb)*2*32 + ksi*32 + lane
__device__ uint4 g_Wh[NCHUNK * 2 * 8 * 2 * 32];   // 8192 uint4 = 128KB

struct XPtrs { const float* p[12]; };

__device__ __forceinline__ uint32_t pack_h2(float lo, float hi) {
    uint32_t r;
    asm("cvt.rn.f16x2.f32 %0, %1, %2;" : "=r"(r) : "f"(hi), "f"(lo));
    return r;
}
__device__ __forceinline__ void mma_f16(float& d0, float& d1, float& d2, float& d3,
                                        uint32_t a0, uint32_t a1, uint32_t a2, uint32_t a3,
                                        uint32_t b0, uint32_t b1) {
    asm volatile(
        "mma.sync.aligned.m16n8k16.row.col.f32.f16.f16.f32 "
        "{%0,%1,%2,%3},{%4,%5,%6,%7},{%8,%9},{%0,%1,%2,%3};"
        : "+f"(d0), "+f"(d1), "+f"(d2), "+f"(d3)
        : "r"(a0), "r"(a1), "r"(a2), "r"(a3), "r"(b0), "r"(b1));
}
__device__ __forceinline__ void cp16(void* s, const void* g) {
    uint32_t sa = (uint32_t)__cvta_generic_to_shared(s);
    asm volatile("cp.async.cg.shared.global [%0], [%1], 16;\n" :: "r"(sa), "l"(g));
}

// ---- pre-kernel: pack W[c][o] -> fp16 fragment quads ----
// quad u: lane=u&31, ksi=(u>>5)&1, mb=(u>>6)&7, cht=(u>>9)&1, ch=u>>10
// a0={W[k][m],W[k+1][m]} a1={..m+8} a2={W[k+8][m],W[k+9][m]} a3={..m+8}, k=ch*32+ksi*16+2*tig
__global__ void wpack_kernel(const float* __restrict__ W) {
    int u    = blockIdx.x * 256 + threadIdx.x;    // 0..8191
    int lane = u & 31;
    int ksi  = (u >> 5) & 1;
    int mb   = (u >> 6) & 7;
    int cht  = (u >> 9) & 1;
    int ch   = u >> 10;
    int gid = lane >> 2, tig = lane & 3;
    int m = cht * 128 + mb * 16 + gid;
    int k = ch * KB + ksi * 16 + 2 * tig;
    uint4 q;
    q.x = pack_h2(W[k * C_OUT + m],           W[(k + 1) * C_OUT + m]);
    q.y = pack_h2(W[k * C_OUT + m + 8],       W[(k + 1) * C_OUT + m + 8]);
    q.z = pack_h2(W[(k + 8) * C_OUT + m],     W[(k + 9) * C_OUT + m]);
    q.w = pack_h2(W[(k + 8) * C_OUT + m + 8], W[(k + 9) * C_OUT + m + 8]);
    g_Wh[u] = q;
}

// ---- main kernel ----
__global__ void __launch_bounds__(256, 2)
conv_interleave_kernel(XPtrs xs, const float* __restrict__ bg, float* __restrict__ out)
{
    extern __shared__ char smem[];

    const int tid  = threadIdx.x;
    const int lane = tid & 31;
    const int warp = tid >> 5;        // 0..7
    const int gid  = lane >> 2;
    const int tig  = lane & 3;

    // pair out-channel halves of one pixel tile adjacently -> co-resident, X hits L2
    const int bx  = blockIdx.x;       // 0..255
    const int p0  = (bx >> 1) * 128;
    const int cht = bx & 1;
    const int z   = blockIdx.y;       // 0..23
    const int ii  = z >> 1;
    const int bb  = z & 1;
    const float* Xg = xs.p[ii] + (size_t)bb * (C_IN * PIXN);

    const int warp_m = (warp >> 2) * 64;    // local out-channel base (0 or 64)
    const int wmb    = (warp >> 2) * 4;     // local m16-block base
    const int warp_n = (warp & 3) * 32;     // pixel base (0..96)

    // X loader geometry: thread -> (k2 row, 8-pixel group)
    const int lk2 = tid >> 4;         // 0..15
    const int lnb = (tid & 15) * 8;   // 0..120

    float d[4][4][4];
    #pragma unroll
    for (int mb = 0; mb < 4; ++mb)
        #pragma unroll
        for (int nb = 0; nb < 4; ++nb)
            #pragma unroll
            for (int r = 0; r < 4; ++r) d[mb][nb][r] = 0.0f;

    auto load_W = [&](int ch) {                  // cp.async, pre-packed fp16 quads
        char* wdst = smem + (ch % NSTAGE) * STAGE_B;
        const uint4* wsrc = g_Wh + (ch * 2 + cht) * 512;
        cp16(wdst + tid * 16,         wsrc + tid);
        cp16(wdst + (256 + tid) * 16, wsrc + 256 + tid);
        asm volatile("cp.async.commit_group;");
    };
    auto ldg_X = [&](int ch, float4* r) {        // 2 rows x 8 pixels, fp32
        const float* base = Xg + (size_t)(ch * KB + 2 * lk2) * PIXN + p0 + lnb;
        r[0] = *(const float4*)(base);
        r[1] = *(const float4*)(base + 4);
        r[2] = *(const float4*)(base + PIXN);
        r[3] = *(const float4*)(base + PIXN + 4);
    };
    auto sts_X = [&](int ch, const float4* r) {  // pack (k,k+1) pairs -> fp16x2
        uint32_t* xdst = (uint32_t*)(smem + (ch % NSTAGE) * STAGE_B + W_STAGE);
        uint32_t q[8];
        q[0] = pack_h2(r[0].x, r[2].x); q[1] = pack_h2(r[0].y, r[2].y);
        q[2] = pack_h2(r[0].z, r[2].z); q[3] = pack_h2(r[0].w, r[2].w);
        q[4] = pack_h2(r[1].x, r[3].x); q[5] = pack_h2(r[1].y, r[3].y);
        q[6] = pack_h2(r[1].z, r[3].z); q[7] = pack_h2(r[1].w, r[3].w);
        *(uint4*)(xdst + lk2 * RPXH + lnb)     = make_uint4(q[0], q[1], q[2], q[3]);
        *(uint4*)(xdst + lk2 * RPXH + lnb + 4) = make_uint4(q[4], q[5], q[6], q[7]);
    };

    // ---- prologue ----
    load_W(0);
    load_W(1);
    {
        float4 r[4];
        ldg_X(0, r);
        sts_X(0, r);
    }

    // ---- mainloop ----
    #pragma unroll 1
    for (int ch = 0; ch < NCHUNK; ++ch) {
        if (ch >= NCHUNK - 2) asm volatile("cp.async.wait_group 0;");
        else                  asm volatile("cp.async.wait_group 1;");
        __syncthreads();    // W(ch)+X(ch) visible; all warps past stages being refilled

        if (ch + 2 < NCHUNK) load_W(ch + 2);

        float4 xr[4];
        if (ch + 1 < NCHUNK) ldg_X(ch + 1, xr);

        const uint4*    Wf = (const uint4*)(smem + (ch % NSTAGE) * STAGE_B);
        const uint32_t* Xh = (const uint32_t*)(smem + (ch % NSTAGE) * STAGE_B + W_STAGE);

        #pragma unroll
        for (int ksi = 0; ksi < 2; ++ksi) {
            // A fragments: one LDS.128 per m16-block (covers full k16)
            uint4 aq[4];
            #pragma unroll
            for (int mb = 0; mb < 4; ++mb)
                aq[mb] = Wf[((wmb + mb) * 2 + ksi) * 32 + lane];

            // B fragments: fp16x2 pairs, conflict-free LDS.32
            uint32_t bt[8];
            #pragma unroll
            for (int nb = 0; nb < 4; ++nb) {
                const int n = warp_n + nb * 8 + gid;
                bt[2 * nb]     = Xh[(ksi * 8 + tig)     * RPXH + n];
                bt[2 * nb + 1] = Xh[(ksi * 8 + tig + 4) * RPXH + n];
            }

            #pragma unroll
            for (int mb = 0; mb < 4; ++mb) {
                #pragma unroll
                for (int nb = 0; nb < 4; ++nb)
                    mma_f16(d[mb][nb][0], d[mb][nb][1], d[mb][nb][2], d[mb][nb][3],
                            aq[mb].x, aq[mb].y, aq[mb].z, aq[mb].w,
                            bt[2 * nb], bt[2 * nb + 1]);
            }
        }

        if (ch + 1 < NCHUNK) sts_X(ch + 1, xr);
        // no bottom barrier: next iteration's top barrier publishes the STS
    }

    // ---- epilogue: interleaved scatter + bias*count ----
    #pragma unroll
    for (int mb = 0; mb < 4; ++mb) {
        const int o = cht * 128 + warp_m + mb * 16 + gid;
        const float bv0 = __ldg(bg + o);
        const float bv1 = __ldg(bg + o + 8);
        #pragma unroll
        for (int nb = 0; nb < 4; ++nb) {
            const int p = p0 + warp_n + nb * 8 + 2 * tig;
            const int h = p >> 8;
            const int w = p & 255;
            const int r = 12 * h + ii;
            const int cnt = min(11, r) - max(0, r - (HOUTN - 12)) + 1;
            const float fc = (float)cnt;
            const float bias0 = bv0 * fc;
            const float bias1 = bv1 * fc;
            const size_t base = ((size_t)(bb * C_OUT + o) * HOUTN + r) * WwN + w;
            float2 v0 = make_float2(d[mb][nb][0] + bias0, d[mb][nb][1] + bias0);
            float2 v1 = make_float2(d[mb][nb][2] + bias1, d[mb][nb][3] + bias1);
            *reinterpret_cast<float2*>(out + base) = v0;
            *reinterpret_cast<float2*>(out + base + (size_t)8 * HOUTN * WwN) = v1;
        }
    }
}

extern "C" void kernel_launch(void* const* d_in, const int* in_sizes, int n_in,
                              void* d_out, int out_size)
{
    (void)in_sizes; (void)n_in; (void)out_size;

    XPtrs xs;
    for (int i = 0; i < 12; ++i) xs.p[i] = (const float*)d_in[i];
    const float* W = (const float*)d_in[12];
    const float* b = (const float*)d_in[13];
    float* out = (float*)d_out;

    wpack_kernel<<<32, 256>>>(W);

    cudaFuncSetAttribute(conv_interleave_kernel,
                         cudaFuncAttributeMaxDynamicSharedMemorySize, SMEM_BYTES);
    dim3 grid(256, 24, 1);   // (pixel-tile, ch-half) pairs x 24
    conv_interleave_kernel<<<grid, 256, SMEM_BYTES>>>(xs, b, out);
}

// round 11
// speedup vs baseline: 1.4525x; 1.0015x over previous
#include <cuda_runtime.h>
#include <cuda_fp16.h>
#include <cstdint>

// ---------------- problem constants ----------------
#define C_IN   256
#define C_OUT  256
#define PIXN   16384          // 64*256 pixels per (tensor, batch)
#define HOUTN  768
#define WwN    256

// ---------------- tiling ----------------
// CTA: 128 out-ch x 128 pixels, K chunks of 32 (2 x k16 steps). 8 warps, warp tile 64x32.
// fp16 m16n8k16 HMMA, fp32 accumulate. 3-stage W (cp.async) + 1-ahead X (LDG/cvt/STS).
#define KB      32
#define NCHUNK  8
#define RPXH    136           // X row stride in uint32(fp16x2): 136 % 32 == 8 -> conflict-free
#define W_STAGE 8192          // fp16 fragment-packed W chunk: 512 uint4
#define X_STAGE (16*RPXH*4)   // 16 k2-rows x 136 uint32 = 8704 B
#define STAGE_B (W_STAGE + X_STAGE)     // 16896
#define NSTAGE  3
#define SMEM_BYTES (NSTAGE * STAGE_B)   // 50688 -> 2 CTAs/SM (reg-capped)

// W fragment quads, fp16x2: uint4 index = ((ch*2+cht)*8 + mb)*2*32 + ksi*32 + lane
__device__ uint4 g_Wh[NCHUNK * 2 * 8 * 2 * 32];   // 8192 uint4 = 128KB

struct XPtrs { const float* p[12]; };

__device__ __forceinline__ uint32_t pack_h2(float lo, float hi) {
    uint32_t r;
    asm("cvt.rn.f16x2.f32 %0, %1, %2;" : "=r"(r) : "f"(hi), "f"(lo));
    return r;
}
__device__ __forceinline__ void mma_f16(float& d0, float& d1, float& d2, float& d3,
                                        uint32_t a0, uint32_t a1, uint32_t a2, uint32_t a3,
                                        uint32_t b0, uint32_t b1) {
    asm volatile(
        "mma.sync.aligned.m16n8k16.row.col.f32.f16.f16.f32 "
        "{%0,%1,%2,%3},{%4,%5,%6,%7},{%8,%9},{%0,%1,%2,%3};"
        : "+f"(d0), "+f"(d1), "+f"(d2), "+f"(d3)
        : "r"(a0), "r"(a1), "r"(a2), "r"(a3), "r"(b0), "r"(b1));
}
__device__ __forceinline__ void cp16(void* s, const void* g) {
    uint32_t sa = (uint32_t)__cvta_generic_to_shared(s);
    asm volatile("cp.async.cg.shared.global [%0], [%1], 16;\n" :: "r"(sa), "l"(g));
}

// ---- pre-kernel: pack W[c][o] -> fp16 fragment quads ----
// quad u: lane=u&31, ksi=(u>>5)&1, mb=(u>>6)&7, cht=(u>>9)&1, ch=u>>10
// a0={W[k][m],W[k+1][m]} a1={..m+8} a2={W[k+8][m],W[k+9][m]} a3={..m+8}, k=ch*32+ksi*16+2*tig
__global__ void wpack_kernel(const float* __restrict__ W) {
    int u    = blockIdx.x * 256 + threadIdx.x;    // 0..8191
    int lane = u & 31;
    int ksi  = (u >> 5) & 1;
    int mb   = (u >> 6) & 7;
    int cht  = (u >> 9) & 1;
    int ch   = u >> 10;
    int gid = lane >> 2, tig = lane & 3;
    int m = cht * 128 + mb * 16 + gid;
    int k = ch * KB + ksi * 16 + 2 * tig;
    uint4 q;
    q.x = pack_h2(W[k * C_OUT + m],           W[(k + 1) * C_OUT + m]);
    q.y = pack_h2(W[k * C_OUT + m + 8],       W[(k + 1) * C_OUT + m + 8]);
    q.z = pack_h2(W[(k + 8) * C_OUT + m],     W[(k + 9) * C_OUT + m]);
    q.w = pack_h2(W[(k + 8) * C_OUT + m + 8], W[(k + 9) * C_OUT + m + 8]);
    g_Wh[u] = q;
}

// ---- main kernel ----
__global__ void __launch_bounds__(256, 2)
conv_interleave_kernel(XPtrs xs, const float* __restrict__ bg, float* __restrict__ out)
{
    extern __shared__ char smem[];

    const int tid  = threadIdx.x;
    const int lane = tid & 31;
    const int warp = tid >> 5;        // 0..7
    const int gid  = lane >> 2;
    const int tig  = lane & 3;

    // pair out-channel halves of one pixel tile adjacently -> co-resident, X hits L2
    const int bx  = blockIdx.x;       // 0..255
    const int p0  = (bx >> 1) * 128;
    const int cht = bx & 1;
    const int z   = blockIdx.y;       // 0..23
    const int ii  = z >> 1;
    const int bb  = z & 1;
    const float* Xg = xs.p[ii] + (size_t)bb * (C_IN * PIXN);

    const int warp_m = (warp >> 2) * 64;    // local out-channel base (0 or 64)
    const int wmb    = (warp >> 2) * 4;     // local m16-block base
    const int warp_n = (warp & 3) * 32;     // pixel base (0..96)

    // X loader geometry: thread -> (k2 row, 8-pixel group)
    const int lk2 = tid >> 4;         // 0..15
    const int lnb = (tid & 15) * 8;   // 0..120

    float d[4][4][4];
    #pragma unroll
    for (int mb = 0; mb < 4; ++mb)
        #pragma unroll
        for (int nb = 0; nb < 4; ++nb)
            #pragma unroll
            for (int r = 0; r < 4; ++r) d[mb][nb][r] = 0.0f;

    auto load_W = [&](int ch) {                  // cp.async, pre-packed fp16 quads
        char* wdst = smem + (ch % NSTAGE) * STAGE_B;
        const uint4* wsrc = g_Wh + (ch * 2 + cht) * 512;
        cp16(wdst + tid * 16,         wsrc + tid);
        cp16(wdst + (256 + tid) * 16, wsrc + 256 + tid);
        asm volatile("cp.async.commit_group;");
    };
    auto ldg_X = [&](int ch, float4* r) {        // 2 rows x 8 pixels, fp32
        const float* base = Xg + (size_t)(ch * KB + 2 * lk2) * PIXN + p0 + lnb;
        r[0] = *(const float4*)(base);
        r[1] = *(const float4*)(base + 4);
        r[2] = *(const float4*)(base + PIXN);
        r[3] = *(const float4*)(base + PIXN + 4);
    };
    auto sts_X = [&](int ch, const float4* r) {  // pack (k,k+1) pairs -> fp16x2
        uint32_t* xdst = (uint32_t*)(smem + (ch % NSTAGE) * STAGE_B + W_STAGE);
        uint32_t q[8];
        q[0] = pack_h2(r[0].x, r[2].x); q[1] = pack_h2(r[0].y, r[2].y);
        q[2] = pack_h2(r[0].z, r[2].z); q[3] = pack_h2(r[0].w, r[2].w);
        q[4] = pack_h2(r[1].x, r[3].x); q[5] = pack_h2(r[1].y, r[3].y);
        q[6] = pack_h2(r[1].z, r[3].z); q[7] = pack_h2(r[1].w, r[3].w);
        *(uint4*)(xdst + lk2 * RPXH + lnb)     = make_uint4(q[0], q[1], q[2], q[3]);
        *(uint4*)(xdst + lk2 * RPXH + lnb + 4) = make_uint4(q[4], q[5], q[6], q[7]);
    };

    // ---- prologue ----
    load_W(0);
    load_W(1);
    {
        float4 r[4];
        ldg_X(0, r);
        sts_X(0, r);
    }

    // ---- mainloop ----
    #pragma unroll 1
    for (int ch = 0; ch < NCHUNK; ++ch) {
        if (ch >= NCHUNK - 2) asm volatile("cp.async.wait_group 0;");
        else                  asm volatile("cp.async.wait_group 1;");
        __syncthreads();    // W(ch)+X(ch) visible; all warps past stages being refilled

        if (ch + 2 < NCHUNK) load_W(ch + 2);

        float4 xr[4];
        if (ch + 1 < NCHUNK) ldg_X(ch + 1, xr);

        const uint4*    Wf = (const uint4*)(smem + (ch % NSTAGE) * STAGE_B);
        const uint32_t* Xh = (const uint32_t*)(smem + (ch % NSTAGE) * STAGE_B + W_STAGE);

        #pragma unroll
        for (int ksi = 0; ksi < 2; ++ksi) {
            // A fragments: one LDS.128 per m16-block (covers full k16)
            uint4 aq[4];
            #pragma unroll
            for (int mb = 0; mb < 4; ++mb)
                aq[mb] = Wf[((wmb + mb) * 2 + ksi) * 32 + lane];

            // B fragments: fp16x2 pairs, conflict-free LDS.32
            uint32_t bt[8];
            #pragma unroll
            for (int nb = 0; nb < 4; ++nb) {
                const int n = warp_n + nb * 8 + gid;
                bt[2 * nb]     = Xh[(ksi * 8 + tig)     * RPXH + n];
                bt[2 * nb + 1] = Xh[(ksi * 8 + tig + 4) * RPXH + n];
            }

            #pragma unroll
            for (int mb = 0; mb < 4; ++mb) {
                #pragma unroll
                for (int nb = 0; nb < 4; ++nb)
                    mma_f16(d[mb][nb][0], d[mb][nb][1], d[mb][nb][2], d[mb][nb][3],
                            aq[mb].x, aq[mb].y, aq[mb].z, aq[mb].w,
                            bt[2 * nb], bt[2 * nb + 1]);
            }
        }

        if (ch + 1 < NCHUNK) sts_X(ch + 1, xr);
        // no bottom barrier: next iteration's top barrier publishes the STS
    }

    // ---- epilogue: interleaved scatter + bias*count ----
    #pragma unroll
    for (int mb = 0; mb < 4; ++mb) {
        const int o = cht * 128 + warp_m + mb * 16 + gid;
        const float bv0 = __ldg(bg + o);
        const float bv1 = __ldg(bg + o + 8);
        #pragma unroll
        for (int nb = 0; nb < 4; ++nb) {
            const int p = p0 + warp_n + nb * 8 + 2 * tig;
            const int h = p >> 8;
            const int w = p & 255;
            const int r = 12 * h + ii;
            const int cnt = min(11, r) - max(0, r - (HOUTN - 12)) + 1;
            const float fc = (float)cnt;
            const float bias0 = bv0 * fc;
            const float bias1 = bv1 * fc;
            const size_t base = ((size_t)(bb * C_OUT + o) * HOUTN + r) * WwN + w;
            float2 v0 = make_float2(d[mb][nb][0] + bias0, d[mb][nb][1] + bias0);
            float2 v1 = make_float2(d[mb][nb][2] + bias1, d[mb][nb][3] + bias1);
            *reinterpret_cast<float2*>(out + base) = v0;
            *reinterpret_cast<float2*>(out + base + (size_t)8 * HOUTN * WwN) = v1;
        }
    }
}

extern "C" void kernel_launch(void* const* d_in, const int* in_sizes, int n_in,
                              void* d_out, int out_size)
{
    (void)in_sizes; (void)n_in; (void)out_size;

    XPtrs xs;
    for (int i = 0; i < 12; ++i) xs.p[i] = (const float*)d_in[i];
    const float* W = (const float*)d_in[12];
    const float* b = (const float*)d_in[13];
    float* out = (float*)d_out;

    wpack_kernel<<<32, 256>>>(W);

    cudaFuncSetAttribute(conv_interleave_kernel,
                         cudaFuncAttributeMaxDynamicSharedMemorySize, SMEM_BYTES);
    dim3 grid(256, 24, 1);   // (pixel-tile, ch-half) pairs x 24
    conv_interleave_kernel<<<grid, 256, SMEM_BYTES>>>(xs, b, out);
}

// round 12
// speedup vs baseline: 1.5102x; 1.0397x over previous
#include <cuda_runtime.h>
#include <cuda_fp16.h>
#include <cstdint>

// ---------------- problem constants ----------------
#define C_IN   256
#define C_OUT  256
#define PIXN   16384          // 64*256 pixels per (tensor, batch)
#define HOUTN  768
#define WwN    256

// ---------------- tiling ----------------
// CTA: 128 out-ch x 128 pixels, 4 warps, warp tile 64x64. K chunks of 32 (2 x k16).
// fp16 m16n8k16 HMMA, fp32 accumulate. 3-stage W (cp.async) + 1-ahead X (dense LDG/cvt/STS).
#define KB      32
#define NCHUNK  8
#define RPXH    136           // X row stride in uint32(fp16x2): 136 % 32 == 8 -> conflict-free reads
#define W_STAGE 8192          // fp16 fragment-packed W chunk: 512 uint4 (128m x 32k)
#define X_STAGE (16*RPXH*4)   // 16 k2-rows x 136 uint32 = 8704 B
#define STAGE_B (W_STAGE + X_STAGE)     // 16896
#define NSTAGE  3
#define SMEM_BYTES (NSTAGE * STAGE_B)   // 50688 -> 2 CTAs/SM

// W fragment quads, fp16x2: uint4 index = ((ch*2+cht)*8 + mb)*2*32 + ksi*32 + lane
__device__ uint4 g_Wh[NCHUNK * 2 * 8 * 2 * 32];   // 8192 uint4 = 128KB

struct XPtrs { const float* p[12]; };

__device__ __forceinline__ uint32_t pack_h2(float lo, float hi) {
    uint32_t r;
    asm("cvt.rn.f16x2.f32 %0, %1, %2;" : "=r"(r) : "f"(hi), "f"(lo));
    return r;
}
__device__ __forceinline__ void mma_f16(float& d0, float& d1, float& d2, float& d3,
                                        uint32_t a0, uint32_t a1, uint32_t a2, uint32_t a3,
                                        uint32_t b0, uint32_t b1) {
    asm volatile(
        "mma.sync.aligned.m16n8k16.row.col.f32.f16.f16.f32 "
        "{%0,%1,%2,%3},{%4,%5,%6,%7},{%8,%9},{%0,%1,%2,%3};"
        : "+f"(d0), "+f"(d1), "+f"(d2), "+f"(d3)
        : "r"(a0), "r"(a1), "r"(a2), "r"(a3), "r"(b0), "r"(b1));
}
__device__ __forceinline__ void cp16(void* s, const void* g) {
    uint32_t sa = (uint32_t)__cvta_generic_to_shared(s);
    asm volatile("cp.async.cg.shared.global [%0], [%1], 16;\n" :: "r"(sa), "l"(g));
}

// ---- pre-kernel: pack W[c][o] -> fp16 fragment quads ----
// quad u: lane=u&31, ksi=(u>>5)&1, mb=(u>>6)&7, cht=(u>>9)&1, ch=u>>10
// a0={W[k][m],W[k+1][m]} a1={..m+8} a2={W[k+8][m],W[k+9][m]} a3={..m+8}, k=ch*32+ksi*16+2*tig
__global__ void wpack_kernel(const float* __restrict__ W) {
    int u    = blockIdx.x * 256 + threadIdx.x;    // 0..8191
    int lane = u & 31;
    int ksi  = (u >> 5) & 1;
    int mb   = (u >> 6) & 7;
    int cht  = (u >> 9) & 1;
    int ch   = u >> 10;
    int gid = lane >> 2, tig = lane & 3;
    int m = cht * 128 + mb * 16 + gid;
    int k = ch * KB + ksi * 16 + 2 * tig;
    uint4 q;
    q.x = pack_h2(W[k * C_OUT + m],           W[(k + 1) * C_OUT + m]);
    q.y = pack_h2(W[k * C_OUT + m + 8],       W[(k + 1) * C_OUT + m + 8]);
    q.z = pack_h2(W[(k + 8) * C_OUT + m],     W[(k + 9) * C_OUT + m]);
    q.w = pack_h2(W[(k + 8) * C_OUT + m + 8], W[(k + 9) * C_OUT + m + 8]);
    g_Wh[u] = q;
}

// ---- main kernel ----
__global__ void __launch_bounds__(128, 2)
conv_interleave_kernel(XPtrs xs, const float* __restrict__ bg, float* __restrict__ out)
{
    extern __shared__ char smem[];

    const int tid  = threadIdx.x;     // 0..127
    const int lane = tid & 31;
    const int warp = tid >> 5;        // 0..3
    const int gid  = lane >> 2;
    const int tig  = lane & 3;

    // pair out-channel halves of one pixel tile adjacently -> co-resident, X hits L2
    const int bx  = blockIdx.x;       // 0..255
    const int p0  = (bx >> 1) * 128;
    const int cht = bx & 1;
    const int z   = blockIdx.y;       // 0..23
    const int ii  = z >> 1;
    const int bb  = z & 1;
    const float* Xg = xs.p[ii] + (size_t)bb * (C_IN * PIXN);

    const int warp_m = (warp >> 1) * 64;    // local out-channel base (0 or 64)
    const int wmb    = (warp >> 1) * 4;     // local m16-block base
    const int warp_n = (warp & 1) * 64;     // pixel base (0 or 64)

    // X loader geometry: kp = k2-row (0..15), g = px group; dense 128B lines per LDG
    const int kp = tid >> 3;          // 0..15
    const int gX = tid & 7;           // 0..7

    float d[4][8][4];
    #pragma unroll
    for (int mb = 0; mb < 4; ++mb)
        #pragma unroll
        for (int nb = 0; nb < 8; ++nb)
            #pragma unroll
            for (int r = 0; r < 4; ++r) d[mb][nb][r] = 0.0f;

    auto load_W = [&](int ch) {                  // cp.async, pre-packed fp16 quads
        char* wdst = smem + (ch % NSTAGE) * STAGE_B;
        const uint4* wsrc = g_Wh + (ch * 2 + cht) * 512;
        #pragma unroll
        for (int it = 0; it < 4; ++it)
            cp16(wdst + (it * 128 + tid) * 16, wsrc + it * 128 + tid);
        asm volatile("cp.async.commit_group;");
    };
    auto ldg_X = [&](int ch, float4* ra, float4* rb) {   // dense: px = gX*4 + 32j
        const float* baseA = Xg + (size_t)(ch * KB + 2 * kp) * PIXN + p0 + gX * 4;
        const float* baseB = baseA + PIXN;
        #pragma unroll
        for (int j = 0; j < 4; ++j) {
            ra[j] = *(const float4*)(baseA + 32 * j);
            rb[j] = *(const float4*)(baseB + 32 * j);
        }
    };
    auto sts_X = [&](int ch, const float4* ra, const float4* rb) {
        uint32_t* xdst = (uint32_t*)(smem + (ch % NSTAGE) * STAGE_B + W_STAGE);
        #pragma unroll
        for (int j = 0; j < 4; ++j) {
            uint4 q;
            q.x = pack_h2(ra[j].x, rb[j].x);
            q.y = pack_h2(ra[j].y, rb[j].y);
            q.z = pack_h2(ra[j].z, rb[j].z);
            q.w = pack_h2(ra[j].w, rb[j].w);
            *(uint4*)(xdst + kp * RPXH + gX * 4 + 32 * j) = q;
        }
    };

    // ---- prologue ----
    load_W(0);
    load_W(1);
    {
        float4 ra[4], rb[4];
        ldg_X(0, ra, rb);
        sts_X(0, ra, rb);
    }

    // ---- mainloop ----
    #pragma unroll 1
    for (int ch = 0; ch < NCHUNK; ++ch) {
        if (ch >= NCHUNK - 2) asm volatile("cp.async.wait_group 0;");
        else                  asm volatile("cp.async.wait_group 1;");
        __syncthreads();    // W(ch)+X(ch) visible; all warps past stages being refilled

        if (ch + 2 < NCHUNK) load_W(ch + 2);

        float4 xra[4], xrb[4];
        if (ch + 1 < NCHUNK) ldg_X(ch + 1, xra, xrb);

        const uint4*    Wf = (const uint4*)(smem + (ch % NSTAGE) * STAGE_B);
        const uint32_t* Xh = (const uint32_t*)(smem + (ch % NSTAGE) * STAGE_B + W_STAGE);

        #pragma unroll
        for (int ksi = 0; ksi < 2; ++ksi) {
            // A fragments: one LDS.128 per m16-block (covers full k16)
            uint4 aq[4];
            #pragma unroll
            for (int mb = 0; mb < 4; ++mb)
                aq[mb] = Wf[((wmb + mb) * 2 + ksi) * 32 + lane];

            // B fragments: fp16x2 pairs, conflict-free LDS.32
            uint32_t bt[16];
            #pragma unroll
            for (int nb = 0; nb < 8; ++nb) {
                const int n = warp_n + nb * 8 + gid;
                bt[2 * nb]     = Xh[(ksi * 8 + tig)     * RPXH + n];
                bt[2 * nb + 1] = Xh[(ksi * 8 + tig + 4) * RPXH + n];
            }

            #pragma unroll
            for (int mb = 0; mb < 4; ++mb) {
                #pragma unroll
                for (int nb = 0; nb < 8; ++nb)
                    mma_f16(d[mb][nb][0], d[mb][nb][1], d[mb][nb][2], d[mb][nb][3],
                            aq[mb].x, aq[mb].y, aq[mb].z, aq[mb].w,
                            bt[2 * nb], bt[2 * nb + 1]);
            }
        }

        if (ch + 1 < NCHUNK) sts_X(ch + 1, xra, xrb);
        // next iteration's top barrier publishes the STS
    }

    // ---- epilogue: interleaved scatter + bias*count ----
    #pragma unroll
    for (int mb = 0; mb < 4; ++mb) {
        const int o = cht * 128 + warp_m + mb * 16 + gid;
        const float bv0 = __ldg(bg + o);
        const float bv1 = __ldg(bg + o + 8);
        #pragma unroll
        for (int nb = 0; nb < 8; ++nb) {
            const int p = p0 + warp_n + nb * 8 + 2 * tig;
            const int h = p >> 8;
            const int w = p & 255;
            const int r = 12 * h + ii;
            const int cnt = min(11, r) - max(0, r - (HOUTN - 12)) + 1;
            const float fc = (float)cnt;
            const float bias0 = bv0 * fc;
            const float bias1 = bv1 * fc;
            const size_t base = ((size_t)(bb * C_OUT + o) * HOUTN + r) * WwN + w;
            float2 v0 = make_float2(d[mb][nb][0] + bias0, d[mb][nb][1] + bias0);
            float2 v1 = make_float2(d[mb][nb][2] + bias1, d[mb][nb][3] + bias1);
            *reinterpret_cast<float2*>(out + base) = v0;
            *reinterpret_cast<float2*>(out + base + (size_t)8 * HOUTN * WwN) = v1;
        }
    }
}

extern "C" void kernel_launch(void* const* d_in, const int* in_sizes, int n_in,
                              void* d_out, int out_size)
{
    (void)in_sizes; (void)n_in; (void)out_size;

    XPtrs xs;
    for (int i = 0; i < 12; ++i) xs.p[i] = (const float*)d_in[i];
    const float* W = (const float*)d_in[12];
    const float* b = (const float*)d_in[13];
    float* out = (float*)d_out;

    wpack_kernel<<<32, 256>>>(W);

    cudaFuncSetAttribute(conv_interleave_kernel,
                         cudaFuncAttributeMaxDynamicSharedMemorySize, SMEM_BYTES);
    dim3 grid(256, 24, 1);   // (pixel-tile, ch-half) pairs x 24
    conv_interleave_kernel<<<grid, 128, SMEM_BYTES>>>(xs, b, out);
}

// round 13
// speedup vs baseline: 1.5721x; 1.0410x over previous
#include <cuda_runtime.h>
#include <cuda_fp16.h>
#include <cstdint>

// ---------------- problem constants ----------------
#define C_IN   256
#define C_OUT  256
#define PIXN   16384          // 64*256 pixels per (tensor, batch)
#define HOUTN  768
#define WwN    256

// ---------------- tiling ----------------
// CTA: 128 out-ch x 128 pixels, 4 warps, warp tile 64x64. K chunks of 32 (2 x k16).
// fp16 m16n8k16 HMMA, fp32 accumulate.
// All-cp.async pipeline, 4 stages: W pre-packed fp16 quads + X fp32 (packed to fp16 at LDS).
#define KB      32
#define NCHUNK  8
#define RPXF    132           // X row stride in floats: 132*2 % 32... (264 mod 32 = 8) -> conflict-free
#define W_STAGE 8192          // fp16 fragment-packed W chunk: 512 uint4 (128m x 32k)
#define X_STAGE (KB*RPXF*4)   // 32 rows x 132 floats = 16896 B
#define STAGE_B (W_STAGE + X_STAGE)     // 25088
#define NSTAGE  4
#define SMEM_BYTES (NSTAGE * STAGE_B)   // 100352 -> 2 CTAs/SM

// W fragment quads, fp16x2: uint4 index = ((ch*2+cht)*8 + mb)*2*32 + ksi*32 + lane
__device__ uint4 g_Wh[NCHUNK * 2 * 8 * 2 * 32];   // 8192 uint4 = 128KB

struct XPtrs { const float* p[12]; };

__device__ __forceinline__ uint32_t pack_h2(float lo, float hi) {
    uint32_t r;
    asm("cvt.rn.f16x2.f32 %0, %1, %2;" : "=r"(r) : "f"(hi), "f"(lo));
    return r;
}
__device__ __forceinline__ void mma_f16(float& d0, float& d1, float& d2, float& d3,
                                        uint32_t a0, uint32_t a1, uint32_t a2, uint32_t a3,
                                        uint32_t b0, uint32_t b1) {
    asm volatile(
        "mma.sync.aligned.m16n8k16.row.col.f32.f16.f16.f32 "
        "{%0,%1,%2,%3},{%4,%5,%6,%7},{%8,%9},{%0,%1,%2,%3};"
        : "+f"(d0), "+f"(d1), "+f"(d2), "+f"(d3)
        : "r"(a0), "r"(a1), "r"(a2), "r"(a3), "r"(b0), "r"(b1));
}
__device__ __forceinline__ void cp16(void* s, const void* g) {
    uint32_t sa = (uint32_t)__cvta_generic_to_shared(s);
    asm volatile("cp.async.cg.shared.global [%0], [%1], 16;\n" :: "r"(sa), "l"(g));
}

// ---- pre-kernel: pack W[c][o] -> fp16 fragment quads ----
// quad u: lane=u&31, ksi=(u>>5)&1, mb=(u>>6)&7, cht=(u>>9)&1, ch=u>>10
// a0={W[k][m],W[k+1][m]} a1={..m+8} a2={W[k+8][m],W[k+9][m]} a3={..m+8}, k=ch*32+ksi*16+2*tig
__global__ void wpack_kernel(const float* __restrict__ W) {
    int u    = blockIdx.x * 256 + threadIdx.x;    // 0..8191
    int lane = u & 31;
    int ksi  = (u >> 5) & 1;
    int mb   = (u >> 6) & 7;
    int cht  = (u >> 9) & 1;
    int ch   = u >> 10;
    int gid = lane >> 2, tig = lane & 3;
    int m = cht * 128 + mb * 16 + gid;
    int k = ch * KB + ksi * 16 + 2 * tig;
    uint4 q;
    q.x = pack_h2(W[k * C_OUT + m],           W[(k + 1) * C_OUT + m]);
    q.y = pack_h2(W[k * C_OUT + m + 8],       W[(k + 1) * C_OUT + m + 8]);
    q.z = pack_h2(W[(k + 8) * C_OUT + m],     W[(k + 9) * C_OUT + m]);
    q.w = pack_h2(W[(k + 8) * C_OUT + m + 8], W[(k + 9) * C_OUT + m + 8]);
    g_Wh[u] = q;
}

// ---- main kernel ----
__global__ void __launch_bounds__(128, 2)
conv_interleave_kernel(XPtrs xs, const float* __restrict__ bg, float* __restrict__ out)
{
    extern __shared__ char smem[];

    const int tid  = threadIdx.x;     // 0..127
    const int lane = tid & 31;
    const int warp = tid >> 5;        // 0..3
    const int gid  = lane >> 2;
    const int tig  = lane & 3;

    // pair out-channel halves of one pixel tile adjacently -> co-resident, X hits L2
    const int bx  = blockIdx.x;       // 0..255
    const int p0  = (bx >> 1) * 128;
    const int cht = bx & 1;
    const int z   = blockIdx.y;       // 0..23
    const int ii  = z >> 1;
    const int bb  = z & 1;
    const float* Xg = xs.p[ii] + (size_t)bb * (C_IN * PIXN);

    const int warp_m = (warp >> 1) * 64;    // local out-channel base (0 or 64)
    const int wmb    = (warp >> 1) * 4;     // local m16-block base
    const int warp_n = (warp & 1) * 64;     // pixel base (0 or 64)

    float d[4][8][4];
    #pragma unroll
    for (int mb = 0; mb < 4; ++mb)
        #pragma unroll
        for (int nb = 0; nb < 8; ++nb)
            #pragma unroll
            for (int r = 0; r < 4; ++r) d[mb][nb][r] = 0.0f;

    // ---- async stage loader: W quads + X fp32, one commit group per chunk ----
    auto load_stage = [&](int ch) {
        char* wdst = smem + (ch % NSTAGE) * STAGE_B;
        char* xdst = wdst + W_STAGE;
        const uint4* wsrc = g_Wh + (ch * 2 + cht) * 512;
        #pragma unroll
        for (int it = 0; it < 4; ++it)               // W: 512 x 16B
            cp16(wdst + (it * 128 + tid) * 16, wsrc + it * 128 + tid);
        #pragma unroll
        for (int it = 0; it < 8; ++it) {             // X: 32 rows x 512B (row stride 528B)
            int idx = it * 128 + tid;                 // 0..1023
            int row = idx >> 5, seg = idx & 31;
            cp16(xdst + row * (RPXF * 4) + seg * 16,
                 Xg + (size_t)(ch * KB + row) * PIXN + p0 + seg * 4);
        }
        asm volatile("cp.async.commit_group;");
    };

    // ---- prologue: fill 3 of 4 stages ----
    load_stage(0);
    load_stage(1);
    load_stage(2);

    // ---- mainloop ----
    #pragma unroll 1
    for (int ch = 0; ch < NCHUNK; ++ch) {
        const int rem = NCHUNK - 1 - ch;              // groups that may stay pending
        if (rem >= 2)      asm volatile("cp.async.wait_group 2;");
        else if (rem == 1) asm volatile("cp.async.wait_group 1;");
        else               asm volatile("cp.async.wait_group 0;");
        __syncthreads();   // chunk ch resident; all warps past stage (ch+3)%4 (consumed in ch-1)

        if (ch + 3 < NCHUNK) load_stage(ch + 3);

        const uint4* Wf = (const uint4*)(smem + (ch % NSTAGE) * STAGE_B);
        const float* Xs = (const float*)(smem + (ch % NSTAGE) * STAGE_B + W_STAGE);

        #pragma unroll
        for (int ksi = 0; ksi < 2; ++ksi) {
            // A fragments: one LDS.128 per m16-block (covers full k16), pre-packed fp16
            uint4 aq[4];
            #pragma unroll
            for (int mb = 0; mb < 4; ++mb)
                aq[mb] = Wf[((wmb + mb) * 2 + ksi) * 32 + lane];

            // B fragments: fp32 LDS pairs -> fp16x2 (conflict-free: banks 8*tig+gid)
            const int k0 = ksi * 16 + 2 * tig;
            uint32_t bt[16];
            #pragma unroll
            for (int nb = 0; nb < 8; ++nb) {
                const int n = warp_n + nb * 8 + gid;
                bt[2 * nb]     = pack_h2(Xs[k0 * RPXF + n],       Xs[(k0 + 1) * RPXF + n]);
                bt[2 * nb + 1] = pack_h2(Xs[(k0 + 8) * RPXF + n], Xs[(k0 + 9) * RPXF + n]);
            }

            #pragma unroll
            for (int mb = 0; mb < 4; ++mb) {
                #pragma unroll
                for (int nb = 0; nb < 8; ++nb)
                    mma_f16(d[mb][nb][0], d[mb][nb][1], d[mb][nb][2], d[mb][nb][3],
                            aq[mb].x, aq[mb].y, aq[mb].z, aq[mb].w,
                            bt[2 * nb], bt[2 * nb + 1]);
            }
        }
    }

    // ---- epilogue: interleaved scatter + bias*count ----
    #pragma unroll
    for (int mb = 0; mb < 4; ++mb) {
        const int o = cht * 128 + warp_m + mb * 16 + gid;
        const float bv0 = __ldg(bg + o);
        const float bv1 = __ldg(bg + o + 8);
        #pragma unroll
        for (int nb = 0; nb < 8; ++nb) {
            const int p = p0 + warp_n + nb * 8 + 2 * tig;
            const int h = p >> 8;
            const int w = p & 255;
            const int r = 12 * h + ii;
            const int cnt = min(11, r) - max(0, r - (HOUTN - 12)) + 1;
            const float fc = (float)cnt;
            const float bias0 = bv0 * fc;
            const float bias1 = bv1 * fc;
            const size_t base = ((size_t)(bb * C_OUT + o) * HOUTN + r) * WwN + w;
            float2 v0 = make_float2(d[mb][nb][0] + bias0, d[mb][nb][1] + bias0);
            float2 v1 = make_float2(d[mb][nb][2] + bias1, d[mb][nb][3] + bias1);
            *reinterpret_cast<float2*>(out + base) = v0;
            *reinterpret_cast<float2*>(out + base + (size_t)8 * HOUTN * WwN) = v1;
        }
    }
}

extern "C" void kernel_launch(void* const* d_in, const int* in_sizes, int n_in,
                              void* d_out, int out_size)
{
    (void)in_sizes; (void)n_in; (void)out_size;

    XPtrs xs;
    for (int i = 0; i < 12; ++i) xs.p[i] = (const float*)d_in[i];
    const float* W = (const float*)d_in[12];
    const float* b = (const float*)d_in[13];
    float* out = (float*)d_out;

    wpack_kernel<<<32, 256>>>(W);

    cudaFuncSetAttribute(conv_interleave_kernel,
                         cudaFuncAttributeMaxDynamicSharedMemorySize, SMEM_BYTES);
    dim3 grid(256, 24, 1);   // (pixel-tile, ch-half) pairs x 24
    conv_interleave_kernel<<<grid, 128, SMEM_BYTES>>>(xs, b, out);
}

// round 14
// speedup vs baseline: 1.7194x; 1.0937x over previous
#include <cuda_runtime.h>
#include <cuda_fp16.h>
#include <cstdint>

// ---------------- problem constants ----------------
#define C_IN   256
#define C_OUT  256
#define PIXN   16384          // 64*256 pixels per (tensor, batch)
#define HOUTN  768
#define WwN    256

// ---------------- tiling ----------------
// CTA: 128 out-ch x 128 pixels, 4 warps, warp tile 64x64. K chunks of 32 (2 x k16).
// fp16 m16n8k16 HMMA, fp32 accumulate.
// All-cp.async, 3 stages, 75KB smem + 170-reg cap -> 3 CTAs/SM (12 warps).
#define KB      32
#define NCHUNK  8
#define RPXF    132           // X row stride floats: 2*tig*132 % 32 == 8*tig -> conflict-free
#define W_STAGE 8192          // fp16 fragment-packed W chunk: 512 uint4 (128m x 32k)
#define X_STAGE (KB*RPXF*4)   // 32 rows x 132 floats = 16896 B
#define STAGE_B (W_STAGE + X_STAGE)     // 25088
#define NSTAGE  3
#define SMEM_BYTES (NSTAGE * STAGE_B)   // 75264 -> 3 CTAs/SM

// W fragment quads, fp16x2: uint4 index = ((ch*2+cht)*8 + mb)*2*32 + ksi*32 + lane
__device__ uint4 g_Wh[NCHUNK * 2 * 8 * 2 * 32];   // 8192 uint4 = 128KB

struct XPtrs { const float* p[12]; };

__device__ __forceinline__ uint32_t pack_h2(float lo, float hi) {
    uint32_t r;
    asm("cvt.rn.f16x2.f32 %0, %1, %2;" : "=r"(r) : "f"(hi), "f"(lo));
    return r;
}
__device__ __forceinline__ void mma_f16(float& d0, float& d1, float& d2, float& d3,
                                        uint32_t a0, uint32_t a1, uint32_t a2, uint32_t a3,
                                        uint32_t b0, uint32_t b1) {
    asm volatile(
        "mma.sync.aligned.m16n8k16.row.col.f32.f16.f16.f32 "
        "{%0,%1,%2,%3},{%4,%5,%6,%7},{%8,%9},{%0,%1,%2,%3};"
        : "+f"(d0), "+f"(d1), "+f"(d2), "+f"(d3)
        : "r"(a0), "r"(a1), "r"(a2), "r"(a3), "r"(b0), "r"(b1));
}
__device__ __forceinline__ void cp16(void* s, const void* g) {
    uint32_t sa = (uint32_t)__cvta_generic_to_shared(s);
    asm volatile("cp.async.cg.shared.global [%0], [%1], 16;\n" :: "r"(sa), "l"(g));
}

// ---- pre-kernel: pack W[c][o] -> fp16 fragment quads ----
// quad u: lane=u&31, ksi=(u>>5)&1, mb=(u>>6)&7, cht=(u>>9)&1, ch=u>>10
// a0={W[k][m],W[k+1][m]} a1={..m+8} a2={W[k+8][m],W[k+9][m]} a3={..m+8}, k=ch*32+ksi*16+2*tig
__global__ void wpack_kernel(const float* __restrict__ W) {
    int u    = blockIdx.x * 256 + threadIdx.x;    // 0..8191
    int lane = u & 31;
    int ksi  = (u >> 5) & 1;
    int mb   = (u >> 6) & 7;
    int cht  = (u >> 9) & 1;
    int ch   = u >> 10;
    int gid = lane >> 2, tig = lane & 3;
    int m = cht * 128 + mb * 16 + gid;
    int k = ch * KB + ksi * 16 + 2 * tig;
    uint4 q;
    q.x = pack_h2(W[k * C_OUT + m],           W[(k + 1) * C_OUT + m]);
    q.y = pack_h2(W[k * C_OUT + m + 8],       W[(k + 1) * C_OUT + m + 8]);
    q.z = pack_h2(W[(k + 8) * C_OUT + m],     W[(k + 9) * C_OUT + m]);
    q.w = pack_h2(W[(k + 8) * C_OUT + m + 8], W[(k + 9) * C_OUT + m + 8]);
    g_Wh[u] = q;
}

// ---- main kernel ----
__global__ void __launch_bounds__(128, 3)
conv_interleave_kernel(XPtrs xs, const float* __restrict__ bg, float* __restrict__ out)
{
    extern __shared__ char smem[];

    const int tid  = threadIdx.x;     // 0..127
    const int lane = tid & 31;
    const int warp = tid >> 5;        // 0..3
    const int gid  = lane >> 2;
    const int tig  = lane & 3;

    // pair out-channel halves of one pixel tile adjacently -> co-resident, X hits L2
    const int bx  = blockIdx.x;       // 0..255
    const int p0  = (bx >> 1) * 128;
    const int cht = bx & 1;
    const int z   = blockIdx.y;       // 0..23
    const int ii  = z >> 1;
    const int bb  = z & 1;
    const float* Xg = xs.p[ii] + (size_t)bb * (C_IN * PIXN);

    const int warp_m = (warp >> 1) * 64;    // local out-channel base (0 or 64)
    const int wmb    = (warp >> 1) * 4;     // local m16-block base
    const int warp_n = (warp & 1) * 64;     // pixel base (0 or 64)

    float d[4][8][4];
    #pragma unroll
    for (int mb = 0; mb < 4; ++mb)
        #pragma unroll
        for (int nb = 0; nb < 8; ++nb)
            #pragma unroll
            for (int r = 0; r < 4; ++r) d[mb][nb][r] = 0.0f;

    // ---- async stage loader: W quads + X fp32, one commit group per chunk ----
    auto load_stage = [&](int ch) {
        char* wdst = smem + (ch % NSTAGE) * STAGE_B;
        char* xdst = wdst + W_STAGE;
        const uint4* wsrc = g_Wh + (ch * 2 + cht) * 512;
        #pragma unroll
        for (int it = 0; it < 4; ++it)               // W: 512 x 16B
            cp16(wdst + (it * 128 + tid) * 16, wsrc + it * 128 + tid);
        #pragma unroll
        for (int it = 0; it < 8; ++it) {             // X: 32 rows x 512B (row stride 528B)
            int idx = it * 128 + tid;                 // 0..1023
            int row = idx >> 5, seg = idx & 31;
            cp16(xdst + row * (RPXF * 4) + seg * 16,
                 Xg + (size_t)(ch * KB + row) * PIXN + p0 + seg * 4);
        }
        asm volatile("cp.async.commit_group;");
    };

    // ---- prologue: fill 2 of 3 stages ----
    load_stage(0);
    load_stage(1);

    // ---- mainloop ----
    #pragma unroll 1
    for (int ch = 0; ch < NCHUNK; ++ch) {
        if (ch >= NCHUNK - 2) asm volatile("cp.async.wait_group 0;");
        else                  asm volatile("cp.async.wait_group 1;");
        __syncthreads();   // chunk ch resident; all warps done with chunk ch-1,
                           // whose stage (ch-1)%3 == (ch+2)%3 is the one refilled below

        if (ch + 2 < NCHUNK) load_stage(ch + 2);

        const uint4* Wf = (const uint4*)(smem + (ch % NSTAGE) * STAGE_B);
        const float* Xs = (const float*)(smem + (ch % NSTAGE) * STAGE_B + W_STAGE);

        #pragma unroll
        for (int ksi = 0; ksi < 2; ++ksi) {
            // A fragments: one LDS.128 per m16-block (covers full k16), pre-packed fp16
            uint4 aq[4];
            #pragma unroll
            for (int mb = 0; mb < 4; ++mb)
                aq[mb] = Wf[((wmb + mb) * 2 + ksi) * 32 + lane];

            // B fragments: fp32 LDS pairs -> fp16x2 (conflict-free: banks 8*tig+gid)
            const int k0 = ksi * 16 + 2 * tig;
            uint32_t bt[16];
            #pragma unroll
            for (int nb = 0; nb < 8; ++nb) {
                const int n = warp_n + nb * 8 + gid;
                bt[2 * nb]     = pack_h2(Xs[k0 * RPXF + n],       Xs[(k0 + 1) * RPXF + n]);
                bt[2 * nb + 1] = pack_h2(Xs[(k0 + 8) * RPXF + n], Xs[(k0 + 9) * RPXF + n]);
            }

            #pragma unroll
            for (int mb = 0; mb < 4; ++mb) {
                #pragma unroll
                for (int nb = 0; nb < 8; ++nb)
                    mma_f16(d[mb][nb][0], d[mb][nb][1], d[mb][nb][2], d[mb][nb][3],
                            aq[mb].x, aq[mb].y, aq[mb].z, aq[mb].w,
                            bt[2 * nb], bt[2 * nb + 1]);
            }
        }
    }

    // ---- epilogue: interleaved scatter + bias*count ----
    #pragma unroll
    for (int mb = 0; mb < 4; ++mb) {
        const int o = cht * 128 + warp_m + mb * 16 + gid;
        const float bv0 = __ldg(bg + o);
        const float bv1 = __ldg(bg + o + 8);
        #pragma unroll
        for (int nb = 0; nb < 8; ++nb) {
            const int p = p0 + warp_n + nb * 8 + 2 * tig;
            const int h = p >> 8;
            const int w = p & 255;
            const int r = 12 * h + ii;
            const int cnt = min(11, r) - max(0, r - (HOUTN - 12)) + 1;
            const float fc = (float)cnt;
            const float bias0 = bv0 * fc;
            const float bias1 = bv1 * fc;
            const size_t base = ((size_t)(bb * C_OUT + o) * HOUTN + r) * WwN + w;
            float2 v0 = make_float2(d[mb][nb][0] + bias0, d[mb][nb][1] + bias0);
            float2 v1 = make_float2(d[mb][nb][2] + bias1, d[mb][nb][3] + bias1);
            *reinterpret_cast<float2*>(out + base) = v0;
            *reinterpret_cast<float2*>(out + base + (size_t)8 * HOUTN * WwN) = v1;
        }
    }
}

extern "C" void kernel_launch(void* const* d_in, const int* in_sizes, int n_in,
                              void* d_out, int out_size)
{
    (void)in_sizes; (void)n_in; (void)out_size;

    XPtrs xs;
    for (int i = 0; i < 12; ++i) xs.p[i] = (const float*)d_in[i];
    const float* W = (const float*)d_in[12];
    const float* b = (const float*)d_in[13];
    float* out = (float*)d_out;

    wpack_kernel<<<32, 256>>>(W);

    cudaFuncSetAttribute(conv_interleave_kernel,
                         cudaFuncAttributeMaxDynamicSharedMemorySize, SMEM_BYTES);
    dim3 grid(256, 24, 1);   // (pixel-tile, ch-half) pairs x 24
    conv_interleave_kernel<<<grid, 128, SMEM_BYTES>>>(xs, b, out);
}

// round 15
// speedup vs baseline: 1.9422x; 1.1296x over previous
#include <cuda_runtime.h>
#include <cuda_fp16.h>
#include <cstdint>

// ---------------- problem constants ----------------
#define C_IN   256
#define C_OUT  256
#define PIXN   16384          // 64*256 pixels per (tensor, batch)
#define HOUTN  768
#define WwN    256

// ---------------- tiling ----------------
// CTA: 128 out-ch x 128 pixels, 4 warps, warp tile 64x64. K chunks of 16 (1 x k16).
// fp16 m16n8k16 HMMA with fp16 accumulate (halved accum regs -> 4 CTAs/SM, 16 warps).
// All-cp.async, 3 stages.
#define KB      16
#define NCHUNK  16
#define RPXF    132           // X row stride floats: banks 8*tig+gid -> conflict-free
#define W_STAGE 4096          // fp16 fragment-packed W chunk: 256 uint4 (128m x 16k)
#define X_STAGE (KB*RPXF*4)   // 16 rows x 132 floats = 8448 B
#define STAGE_B (W_STAGE + X_STAGE)     // 12544
#define NSTAGE  3
#define SMEM_BYTES (NSTAGE * STAGE_B)   // 37632 -> 4 CTAs/SM (reg-capped at 128)

// W fragment quads, fp16x2: uint4 index = ((ch*2+cht)*8 + mb)*32 + lane
__device__ uint4 g_Wh[NCHUNK * 2 * 8 * 32];   // 8192 uint4 = 128KB

struct XPtrs { const float* p[12]; };

__device__ __forceinline__ uint32_t pack_h2(float lo, float hi) {
    uint32_t r;
    asm("cvt.rn.f16x2.f32 %0, %1, %2;" : "=r"(r) : "f"(hi), "f"(lo));
    return r;
}
// fp16-accumulate HMMA: D(f16x2 pair) = A*B + D
__device__ __forceinline__ void mma_f16acc(uint32_t& d0, uint32_t& d1,
                                           uint32_t a0, uint32_t a1, uint32_t a2, uint32_t a3,
                                           uint32_t b0, uint32_t b1) {
    asm volatile(
        "mma.sync.aligned.m16n8k16.row.col.f16.f16.f16.f16 "
        "{%0,%1},{%2,%3,%4,%5},{%6,%7},{%0,%1};"
        : "+r"(d0), "+r"(d1)
        : "r"(a0), "r"(a1), "r"(a2), "r"(a3), "r"(b0), "r"(b1));
}
__device__ __forceinline__ void cp16(void* s, const void* g) {
    uint32_t sa = (uint32_t)__cvta_generic_to_shared(s);
    asm volatile("cp.async.cg.shared.global [%0], [%1], 16;\n" :: "r"(sa), "l"(g));
}

// ---- pre-kernel: pack W[c][o] -> fp16 fragment quads (k16 chunks) ----
// quad u: lane=u&31, mb=(u>>5)&7, cht=(u>>8)&1, ch=u>>9
// a0={W[k][m],W[k+1][m]} a1={..m+8} a2={W[k+8][m],W[k+9][m]} a3={..m+8}, k=ch*16+2*tig
__global__ void wpack_kernel(const float* __restrict__ W) {
    int u    = blockIdx.x * 256 + threadIdx.x;    // 0..8191
    int lane = u & 31;
    int mb   = (u >> 5) & 7;
    int cht  = (u >> 8) & 1;
    int ch   = u >> 9;
    int gid = lane >> 2, tig = lane & 3;
    int m = cht * 128 + mb * 16 + gid;
    int k = ch * KB + 2 * tig;
    uint4 q;
    q.x = pack_h2(W[k * C_OUT + m],           W[(k + 1) * C_OUT + m]);
    q.y = pack_h2(W[k * C_OUT + m + 8],       W[(k + 1) * C_OUT + m + 8]);
    q.z = pack_h2(W[(k + 8) * C_OUT + m],     W[(k + 9) * C_OUT + m]);
    q.w = pack_h2(W[(k + 8) * C_OUT + m + 8], W[(k + 9) * C_OUT + m + 8]);
    g_Wh[u] = q;
}

// ---- main kernel ----
__global__ void __launch_bounds__(128, 4)
conv_interleave_kernel(XPtrs xs, const float* __restrict__ bg, float* __restrict__ out)
{
    extern __shared__ char smem[];

    const int tid  = threadIdx.x;     // 0..127
    const int lane = tid & 31;
    const int warp = tid >> 5;        // 0..3
    const int gid  = lane >> 2;
    const int tig  = lane & 3;

    // pair out-channel halves of one pixel tile adjacently -> co-resident, X hits L2
    const int bx  = blockIdx.x;       // 0..255
    const int p0  = (bx >> 1) * 128;
    const int cht = bx & 1;
    const int z   = blockIdx.y;       // 0..23
    const int ii  = z >> 1;
    const int bb  = z & 1;
    const float* Xg = xs.p[ii] + (size_t)bb * (C_IN * PIXN);

    const int warp_m = (warp >> 1) * 64;    // local out-channel base (0 or 64)
    const int wmb    = (warp >> 1) * 4;     // local m16-block base
    const int warp_n = (warp & 1) * 64;     // pixel base (0 or 64)

    // fp16x2 accumulators: da[mb][nb][0] = rows gid cols {2tig,2tig+1}; [1] = rows gid+8
    uint32_t da[4][8][2];
    #pragma unroll
    for (int mb = 0; mb < 4; ++mb)
        #pragma unroll
        for (int nb = 0; nb < 8; ++nb) {
            da[mb][nb][0] = 0u;
            da[mb][nb][1] = 0u;
        }

    // ---- async stage loader: W quads + X fp32, one commit group per chunk ----
    auto load_stage = [&](int ch) {
        char* wdst = smem + (ch % NSTAGE) * STAGE_B;
        char* xdst = wdst + W_STAGE;
        const uint4* wsrc = g_Wh + (ch * 2 + cht) * 256;
        #pragma unroll
        for (int it = 0; it < 2; ++it)               // W: 256 x 16B
            cp16(wdst + (it * 128 + tid) * 16, wsrc + it * 128 + tid);
        #pragma unroll
        for (int it = 0; it < 4; ++it) {             // X: 16 rows x 512B (row stride 528B)
            int idx = it * 128 + tid;                 // 0..511
            int row = idx >> 5, seg = idx & 31;
            cp16(xdst + row * (RPXF * 4) + seg * 16,
                 Xg + (size_t)(ch * KB + row) * PIXN + p0 + seg * 4);
        }
        asm volatile("cp.async.commit_group;");
    };

    // ---- prologue: fill 2 of 3 stages ----
    load_stage(0);
    load_stage(1);

    // ---- mainloop ----
    #pragma unroll 1
    for (int ch = 0; ch < NCHUNK; ++ch) {
        if (ch == NCHUNK - 1) asm volatile("cp.async.wait_group 0;");
        else                  asm volatile("cp.async.wait_group 1;");
        __syncthreads();   // chunk ch resident; all warps done with chunk ch-1,
                           // whose stage (ch-1)%3 == (ch+2)%3 is the one refilled below

        if (ch + 2 < NCHUNK) load_stage(ch + 2);

        const uint4* Wf = (const uint4*)(smem + (ch % NSTAGE) * STAGE_B);
        const float* Xs = (const float*)(smem + (ch % NSTAGE) * STAGE_B + W_STAGE);

        // A fragments: one LDS.128 per m16-block (full k16), pre-packed fp16
        uint4 aq[4];
        #pragma unroll
        for (int mb = 0; mb < 4; ++mb)
            aq[mb] = Wf[(wmb + mb) * 32 + lane];

        // B fragments: fp32 LDS pairs -> fp16x2 (conflict-free: banks 8*tig+gid)
        const int k0 = 2 * tig;
        uint32_t bt[16];
        #pragma unroll
        for (int nb = 0; nb < 8; ++nb) {
            const int n = warp_n + nb * 8 + gid;
            bt[2 * nb]     = pack_h2(Xs[k0 * RPXF + n],       Xs[(k0 + 1) * RPXF + n]);
            bt[2 * nb + 1] = pack_h2(Xs[(k0 + 8) * RPXF + n], Xs[(k0 + 9) * RPXF + n]);
        }

        #pragma unroll
        for (int mb = 0; mb < 4; ++mb) {
            #pragma unroll
            for (int nb = 0; nb < 8; ++nb)
                mma_f16acc(da[mb][nb][0], da[mb][nb][1],
                           aq[mb].x, aq[mb].y, aq[mb].z, aq[mb].w,
                           bt[2 * nb], bt[2 * nb + 1]);
        }
    }

    // ---- epilogue: unpack fp16 accum, add fp32 bias*count, interleaved scatter ----
    #pragma unroll
    for (int mb = 0; mb < 4; ++mb) {
        const int o = cht * 128 + warp_m + mb * 16 + gid;
        const float bv0 = __ldg(bg + o);
        const float bv1 = __ldg(bg + o + 8);
        #pragma unroll
        for (int nb = 0; nb < 8; ++nb) {
            const int p = p0 + warp_n + nb * 8 + 2 * tig;
            const int h = p >> 8;
            const int w = p & 255;
            const int r = 12 * h + ii;
            const int cnt = min(11, r) - max(0, r - (HOUTN - 12)) + 1;
            const float fc = (float)cnt;
            const float bias0 = bv0 * fc;
            const float bias1 = bv1 * fc;
            const float2 f0 = __half22float2(*reinterpret_cast<__half2*>(&da[mb][nb][0]));
            const float2 f1 = __half22float2(*reinterpret_cast<__half2*>(&da[mb][nb][1]));
            const size_t base = ((size_t)(bb * C_OUT + o) * HOUTN + r) * WwN + w;
            float2 v0 = make_float2(f0.x + bias0, f0.y + bias0);
            float2 v1 = make_float2(f1.x + bias1, f1.y + bias1);
            *reinterpret_cast<float2*>(out + base) = v0;
            *reinterpret_cast<float2*>(out + base + (size_t)8 * HOUTN * WwN) = v1;
        }
    }
}

extern "C" void kernel_launch(void* const* d_in, const int* in_sizes, int n_in,
                              void* d_out, int out_size)
{
    (void)in_sizes; (void)n_in; (void)out_size;

    XPtrs xs;
    for (int i = 0; i < 12; ++i) xs.p[i] = (const float*)d_in[i];
    const float* W = (const float*)d_in[12];
    const float* b = (const float*)d_in[13];
    float* out = (float*)d_out;

    wpack_kernel<<<32, 256>>>(W);

    cudaFuncSetAttribute(conv_interleave_kernel,
                         cudaFuncAttributeMaxDynamicSharedMemorySize, SMEM_BYTES);
    dim3 grid(256, 24, 1);   // (pixel-tile, ch-half) pairs x 24
    conv_interleave_kernel<<<grid, 128, SMEM_BYTES>>>(xs, b, out);
}